// round 1
// baseline (speedup 1.0000x reference)
#include <cuda_runtime.h>
#include <cuda_fp16.h>

// Problem constants
#define FH 100
#define FW 100
#define NC 1024
#define NK 7
#define NT 81
#define NTP 96           // padded targets
#define NR 1024
#define NBINS 49
#define KTOT (NBINS*NC)  // 50176
#define KSPLIT 16
#define KPER (KTOT/KSPLIT)  // 3136
#define MTILE 64
#define MT (NR/MTILE)       // 16

// Scratch (device globals; no allocation)
__device__ __half g_xt[FH*FW*NC];                      // 20.5 MB, (HW, C) fp16
__device__ __half g_pool[(size_t)NR*KTOT];             // 103 MB, (R, bin*C) fp16
__device__ __half g_wp[(size_t)KTOT*NTP];              // 9.6 MB, (bin*C, Tpad) fp16
__device__ float  g_partial[(size_t)KSPLIT*NR*NTP];    // 6.3 MB

__device__ __forceinline__ float2 h2f2(unsigned v) {
    __half2 h = *reinterpret_cast<__half2*>(&v);
    return __half22float2(h);
}

// ---------------- Kernel 1: transpose + convert  x(C,HW) f32 -> xt(HW,C) f16
__global__ void k_transpose(const float* __restrict__ x) {
    __shared__ float tile[32][33];
    int p0 = blockIdx.x * 32;
    int c0 = blockIdx.y * 32;
    int tx = threadIdx.x, ty = threadIdx.y;
    #pragma unroll
    for (int j = 0; j < 4; j++) {
        int c = c0 + ty + j*8;
        int p = p0 + tx;
        float v = 0.0f;
        if (p < FH*FW) v = x[c*(FH*FW) + p];
        tile[ty + j*8][tx] = v;
    }
    __syncthreads();
    #pragma unroll
    for (int j = 0; j < 4; j++) {
        int p = p0 + ty + j*8;
        int c = c0 + tx;
        if (p < FH*FW) g_xt[(size_t)p*NC + c] = __float2half(tile[tx][ty + j*8]);
    }
}

// ---------------- Kernel 2: weight permute  conv_w(T*49, C) -> Wp(bin*C, Tpad) f16
__global__ void k_wprep(const float* __restrict__ conv_w) {
    int k = blockIdx.x*256 + threadIdx.x;   // k = bin*NC + c
    if (k >= KTOT) return;
    int bin = k >> 10;
    int c = k & 1023;
    __half* dst = g_wp + (size_t)k*NTP;
    #pragma unroll 3
    for (int t = 0; t < NT; t++) {
        float w = conv_w[((t*NBINS + bin)*NC) + c];
        dst[t] = __float2half(w);
    }
    #pragma unroll
    for (int t = NT; t < NTP; t++) dst[t] = __float2half(0.0f);
}

// ---------------- Kernel 3: PSROIAlign pooling (sum over S*S=4 samples, no mean)
// One CTA per region; 256 threads; thread owns 4 channels (uint2 = 4 halves).
__global__ void k_pool(const float* __restrict__ regions) {
    int r = blockIdx.x;
    int tid = threadIdx.x;
    float4 reg = reinterpret_cast<const float4*>(regions)[r];
    float top  = (reg.x - reg.z*0.5f)*(float)FH;
    float left = (reg.y - reg.w*0.5f)*(float)FW;
    float bh = reg.z*((float)FH/(float)NK);
    float bw = reg.w*((float)FW/(float)NK);
    const uint2* xt = reinterpret_cast<const uint2*>(g_xt);
    uint2* pout = reinterpret_cast<uint2*>(g_pool + (size_t)r*KTOT);

    for (int u = 0; u < NK; u++) {
        int yi0[2], yi1[2]; float wy1a[2];
        #pragma unroll
        for (int s = 0; s < 2; s++) {
            float ys = top + ((float)u + (s ? 0.75f : 0.25f))*bh;
            ys = fminf(fmaxf(ys, 0.0f), 99.0f);
            float yf = floorf(ys);
            int y0 = (int)yf;
            yi0[s] = y0; yi1[s] = min(y0 + 1, 99);
            wy1a[s] = ys - yf;
        }
        for (int v = 0; v < NK; v++) {
            int xi0[2], xi1[2]; float wx1a[2];
            #pragma unroll
            for (int s = 0; s < 2; s++) {
                float xs = left + ((float)v + (s ? 0.75f : 0.25f))*bw;
                xs = fminf(fmaxf(xs, 0.0f), 99.0f);
                float xf = floorf(xs);
                int x0 = (int)xf;
                xi0[s] = x0; xi1[s] = min(x0 + 1, 99);
                wx1a[s] = xs - xf;
            }
            float a0 = 0.f, a1 = 0.f, a2 = 0.f, a3 = 0.f;
            #pragma unroll
            for (int sy = 0; sy < 2; sy++) {
                #pragma unroll
                for (int sx = 0; sx < 2; sx++) {
                    float wy1 = wy1a[sy], wy0 = 1.0f - wy1;
                    float wx1 = wx1a[sx], wx0 = 1.0f - wx1;
                    int b00 = (yi0[sy]*FW + xi0[sx])*(NC/4);
                    int b01 = (yi0[sy]*FW + xi1[sx])*(NC/4);
                    int b10 = (yi1[sy]*FW + xi0[sx])*(NC/4);
                    int b11 = (yi1[sy]*FW + xi1[sx])*(NC/4);
                    uint2 d00 = xt[b00 + tid];
                    uint2 d01 = xt[b01 + tid];
                    uint2 d10 = xt[b10 + tid];
                    uint2 d11 = xt[b11 + tid];
                    float w00 = wy0*wx0, w01v = wy0*wx1, w10 = wy1*wx0, w11 = wy1*wx1;
                    float2 f;
                    f = h2f2(d00.x); a0 += w00*f.x;  a1 += w00*f.y;
                    f = h2f2(d00.y); a2 += w00*f.x;  a3 += w00*f.y;
                    f = h2f2(d01.x); a0 += w01v*f.x; a1 += w01v*f.y;
                    f = h2f2(d01.y); a2 += w01v*f.x; a3 += w01v*f.y;
                    f = h2f2(d10.x); a0 += w10*f.x;  a1 += w10*f.y;
                    f = h2f2(d10.y); a2 += w10*f.x;  a3 += w10*f.y;
                    f = h2f2(d11.x); a0 += w11*f.x;  a1 += w11*f.y;
                    f = h2f2(d11.y); a2 += w11*f.x;  a3 += w11*f.y;
                }
            }
            __half2 ha = __floats2half2_rn(a0, a1);
            __half2 hb = __floats2half2_rn(a2, a3);
            uint2 o;
            o.x = *reinterpret_cast<unsigned*>(&ha);
            o.y = *reinterpret_cast<unsigned*>(&hb);
            pout[(u*NK + v)*(NC/4) + tid] = o;
        }
    }
}

// ---------------- Kernel 4: partial GEMM  P(R, KTOT) @ Wp(KTOT, NTP) -> partial[ks]
// grid = (KSPLIT, MT); 256 threads; CTA tile 64x96, thread tile 4x6.
__global__ void k_gemm() {
    __shared__ float Psm[MTILE][33];
    __shared__ float Wsm[32][NTP];
    int ks = blockIdx.x, mt = blockIdx.y;
    int tid = threadIdx.x;
    int ni = tid & 15, mi = tid >> 4;
    int m0 = mt*MTILE;
    int kbase = ks*KPER;
    float acc[4][6];
    #pragma unroll
    for (int j = 0; j < 4; j++)
        #pragma unroll
        for (int i = 0; i < 6; i++) acc[j][i] = 0.0f;

    for (int kc = 0; kc < KPER; kc += 32) {
        int kg = kbase + kc;
        #pragma unroll
        for (int idx = tid; idx < MTILE*32; idx += 256) {
            int row = idx >> 5, kk = idx & 31;
            Psm[row][kk] = __half2float(g_pool[(size_t)(m0 + row)*KTOT + kg + kk]);
        }
        #pragma unroll
        for (int idx = tid; idx < 32*NTP; idx += 256) {
            int kk = idx / NTP, t = idx - kk*NTP;
            Wsm[kk][t] = __half2float(g_wp[(size_t)(kg + kk)*NTP + t]);
        }
        __syncthreads();
        #pragma unroll 8
        for (int kk = 0; kk < 32; kk++) {
            float pv[4];
            #pragma unroll
            for (int j = 0; j < 4; j++) pv[j] = Psm[mi*4 + j][kk];
            const float2* wr = reinterpret_cast<const float2*>(&Wsm[kk][ni*6]);
            float2 w01 = wr[0], w23 = wr[1], w45 = wr[2];
            float wv[6] = {w01.x, w01.y, w23.x, w23.y, w45.x, w45.y};
            #pragma unroll
            for (int j = 0; j < 4; j++)
                #pragma unroll
                for (int i = 0; i < 6; i++)
                    acc[j][i] += pv[j]*wv[i];
        }
        __syncthreads();
    }
    #pragma unroll
    for (int j = 0; j < 4; j++) {
        int rg = m0 + mi*4 + j;
        #pragma unroll
        for (int i = 0; i < 6; i++)
            g_partial[((size_t)ks*NR + rg)*NTP + ni*6 + i] = acc[j][i];
    }
}

// ---------------- Kernel 5: reduce K-splits, apply 1/196 mean + bias mean
__global__ void k_reduce(const float* __restrict__ conv_b, float* __restrict__ out) {
    int idx = blockIdx.x*256 + threadIdx.x;
    if (idx >= NR*NT) return;
    int r = idx / NT, t = idx - r*NT;
    float s = 0.0f;
    #pragma unroll
    for (int ks = 0; ks < KSPLIT; ks++)
        s += g_partial[((size_t)ks*NR + r)*NTP + t];
    s *= (1.0f/196.0f);
    float bm = 0.0f;
    for (int b = 0; b < NBINS; b++) bm += conv_b[t*NBINS + b];
    out[idx] = s + bm*(1.0f/49.0f);
}

extern "C" void kernel_launch(void* const* d_in, const int* in_sizes, int n_in,
                              void* d_out, int out_size) {
    const float* x       = (const float*)d_in[0];   // (1024, 100, 100)
    const float* regions = (const float*)d_in[1];   // (1024, 4)
    const float* conv_w  = (const float*)d_in[2];   // (3969, 1024)
    const float* conv_b  = (const float*)d_in[3];   // (3969,)
    float* out = (float*)d_out;                     // (1024, 81)

    k_transpose<<<dim3((FH*FW + 31)/32, NC/32), dim3(32, 8)>>>(x);
    k_wprep<<<(KTOT + 255)/256, 256>>>(conv_w);
    k_pool<<<NR, 256>>>(regions);
    k_gemm<<<dim3(KSPLIT, MT), 256>>>();
    k_reduce<<<(NR*NT + 255)/256, 256>>>(conv_b, out);
}

// round 4
// speedup vs baseline: 3.0906x; 3.0906x over previous
#include <cuda_runtime.h>
#include <cuda_fp16.h>
#include <cstdint>

// Problem constants
#define FH 100
#define FW 100
#define NC 1024
#define NK 7
#define NT 81
#define NTP 96           // padded targets (B rows, zero-padded 81..95)
#define NR 1024
#define NBINS 49
#define KTOT (NBINS*NC)  // 50176

// GEMM tiling (HMMA mma.sync)
#define GKS 16                 // K splits
#define GKPER (KTOT/GKS)       // 3136
#define GMT 8                  // M tiles
#define GMTILE 128
#define KC 64                  // K per pipeline iter
#define NIT (GKPER/KC)         // 49
#define NSTAGE 4

// SMEM layout: per stage, A(128 rows x 144B) then B(96 rows x 144B)
#define ROWB 144               // bytes per smem row (9 x 16B, conflict-free)
#define ROWH 72                // halves per smem row
#define SA_SZ (GMTILE*ROWB)    // 18432
#define SB_SZ (NTP*ROWB)       // 13824
#define STG_SZ (SA_SZ + SB_SZ) // 32256
#define SM_TOTAL (NSTAGE*STG_SZ)  // 129024

// Scratch (device globals; no allocation)
__device__ __half g_xt[FH*FW*NC];                      // (HW, C) fp16
__device__ __half g_pool[(size_t)NR*KTOT];             // (R, bin*C) fp16
__device__ __half g_wp2[(size_t)NTP*KTOT];             // (Tpad, bin*C) fp16 (B, K-major)
__device__ float  g_partial[(size_t)GKS*NR*NTP];

// ---------------- helpers ----------------
__device__ __forceinline__ void cpa16(void* s, const void* g) {
    uint32_t a;
    asm("{ .reg .u64 t; cvta.to.shared.u64 t, %1; cvt.u32.u64 %0, t; }" : "=r"(a) : "l"(s));
    asm volatile("cp.async.cg.shared.global [%0], [%1], 16;" :: "r"(a), "l"(g));
}
__device__ __forceinline__ void cpa_commit() { asm volatile("cp.async.commit_group;"); }
template<int N> __device__ __forceinline__ void cpa_wait() {
    asm volatile("cp.async.wait_group %0;" :: "n"(N));
}
__device__ __forceinline__ void mma16816(float* d, uint32_t a0, uint32_t a1,
                                         uint32_t a2, uint32_t a3,
                                         uint32_t b0, uint32_t b1) {
    asm volatile(
        "mma.sync.aligned.m16n8k16.row.col.f32.f16.f16.f32 "
        "{%0,%1,%2,%3}, {%4,%5,%6,%7}, {%8,%9}, {%0,%1,%2,%3};"
        : "+f"(d[0]), "+f"(d[1]), "+f"(d[2]), "+f"(d[3])
        : "r"(a0), "r"(a1), "r"(a2), "r"(a3), "r"(b0), "r"(b1));
}
__device__ __forceinline__ float2 h2f2(unsigned v) {
    __half2 h = *reinterpret_cast<__half2*>(&v);
    return __half22float2(h);
}

// ---------------- Kernel 1: transpose + convert  x(C,HW) f32 -> xt(HW,C) f16
__global__ void k_transpose(const float* __restrict__ x) {
    __shared__ float tile[32][33];
    int p0 = blockIdx.x * 32;
    int c0 = blockIdx.y * 32;
    int tx = threadIdx.x, ty = threadIdx.y;
    #pragma unroll
    for (int j = 0; j < 4; j++) {
        int c = c0 + ty + j*8;
        int p = p0 + tx;
        float v = 0.0f;
        if (p < FH*FW) v = x[c*(FH*FW) + p];
        tile[ty + j*8][tx] = v;
    }
    __syncthreads();
    #pragma unroll
    for (int j = 0; j < 4; j++) {
        int p = p0 + ty + j*8;
        int c = c0 + tx;
        if (p < FH*FW) g_xt[(size_t)p*NC + c] = __float2half(tile[tx][ty + j*8]);
    }
}

// ---------------- Kernel 2: weight permute  conv_w(T*49, C) f32 -> Wp2(Tpad, bin*C) f16
__global__ void k_wprep2(const float* __restrict__ conv_w) {
    int idx = blockIdx.x*256 + threadIdx.x;   // over NTP * NBINS * 16 (64-ch chunks)
    if (idx >= NTP*NBINS*16) return;
    int t = idx / (NBINS*16);
    int rem = idx - t*(NBINS*16);
    int bin = rem >> 4;
    int c0 = (rem & 15) * 64;
    __half* dst = g_wp2 + (size_t)t*KTOT + bin*NC + c0;
    if (t < NT) {
        const float* src = conv_w + ((size_t)t*NBINS + bin)*NC + c0;
        #pragma unroll
        for (int j = 0; j < 64; j += 8) {
            float4 f0 = *(const float4*)(src + j);
            float4 f1 = *(const float4*)(src + j + 4);
            __half2 h0 = __floats2half2_rn(f0.x, f0.y);
            __half2 h1 = __floats2half2_rn(f0.z, f0.w);
            __half2 h2 = __floats2half2_rn(f1.x, f1.y);
            __half2 h3 = __floats2half2_rn(f1.z, f1.w);
            uint4 o;
            o.x = *reinterpret_cast<unsigned*>(&h0);
            o.y = *reinterpret_cast<unsigned*>(&h1);
            o.z = *reinterpret_cast<unsigned*>(&h2);
            o.w = *reinterpret_cast<unsigned*>(&h3);
            *reinterpret_cast<uint4*>(dst + j) = o;
        }
    } else {
        uint4 z = {0u, 0u, 0u, 0u};
        #pragma unroll
        for (int j = 0; j < 64; j += 8) *reinterpret_cast<uint4*>(dst + j) = z;
    }
}

// ---------------- Kernel 3: PSROIAlign pooling (sum over 2x2 samples, no mean)
__global__ void k_pool(const float* __restrict__ regions) {
    int r = blockIdx.x;
    int tid = threadIdx.x;
    float4 reg = reinterpret_cast<const float4*>(regions)[r];
    float top  = (reg.x - reg.z*0.5f)*(float)FH;
    float left = (reg.y - reg.w*0.5f)*(float)FW;
    float bh = reg.z*((float)FH/(float)NK);
    float bw = reg.w*((float)FW/(float)NK);
    const uint2* xt = reinterpret_cast<const uint2*>(g_xt);
    uint2* pout = reinterpret_cast<uint2*>(g_pool + (size_t)r*KTOT);

    for (int u = 0; u < NK; u++) {
        int yi0[2], yi1[2]; float wy1a[2];
        #pragma unroll
        for (int s = 0; s < 2; s++) {
            float ys = top + ((float)u + (s ? 0.75f : 0.25f))*bh;
            ys = fminf(fmaxf(ys, 0.0f), 99.0f);
            float yf = floorf(ys);
            int y0 = (int)yf;
            yi0[s] = y0; yi1[s] = min(y0 + 1, 99);
            wy1a[s] = ys - yf;
        }
        for (int v = 0; v < NK; v++) {
            int xi0[2], xi1[2]; float wx1a[2];
            #pragma unroll
            for (int s = 0; s < 2; s++) {
                float xs = left + ((float)v + (s ? 0.75f : 0.25f))*bw;
                xs = fminf(fmaxf(xs, 0.0f), 99.0f);
                float xf = floorf(xs);
                int x0 = (int)xf;
                xi0[s] = x0; xi1[s] = min(x0 + 1, 99);
                wx1a[s] = xs - xf;
            }
            float a0 = 0.f, a1 = 0.f, a2 = 0.f, a3 = 0.f;
            #pragma unroll
            for (int sy = 0; sy < 2; sy++) {
                #pragma unroll
                for (int sx = 0; sx < 2; sx++) {
                    float wy1 = wy1a[sy], wy0 = 1.0f - wy1;
                    float wx1 = wx1a[sx], wx0 = 1.0f - wx1;
                    int b00 = (yi0[sy]*FW + xi0[sx])*(NC/4);
                    int b01 = (yi0[sy]*FW + xi1[sx])*(NC/4);
                    int b10 = (yi1[sy]*FW + xi0[sx])*(NC/4);
                    int b11 = (yi1[sy]*FW + xi1[sx])*(NC/4);
                    uint2 d00 = xt[b00 + tid];
                    uint2 d01 = xt[b01 + tid];
                    uint2 d10 = xt[b10 + tid];
                    uint2 d11 = xt[b11 + tid];
                    float w00 = wy0*wx0, w01v = wy0*wx1, w10 = wy1*wx0, w11 = wy1*wx1;
                    float2 f;
                    f = h2f2(d00.x); a0 += w00*f.x;  a1 += w00*f.y;
                    f = h2f2(d00.y); a2 += w00*f.x;  a3 += w00*f.y;
                    f = h2f2(d01.x); a0 += w01v*f.x; a1 += w01v*f.y;
                    f = h2f2(d01.y); a2 += w01v*f.x; a3 += w01v*f.y;
                    f = h2f2(d10.x); a0 += w10*f.x;  a1 += w10*f.y;
                    f = h2f2(d10.y); a2 += w10*f.x;  a3 += w10*f.y;
                    f = h2f2(d11.x); a0 += w11*f.x;  a1 += w11*f.y;
                    f = h2f2(d11.y); a2 += w11*f.x;  a3 += w11*f.y;
                }
            }
            __half2 ha = __floats2half2_rn(a0, a1);
            __half2 hb = __floats2half2_rn(a2, a3);
            uint2 o;
            o.x = *reinterpret_cast<unsigned*>(&ha);
            o.y = *reinterpret_cast<unsigned*>(&hb);
            pout[(u*NK + v)*(NC/4) + tid] = o;
        }
    }
}

// ---------------- Kernel 4: HMMA GEMM  P(R,KTOT) @ Wp2^T(KTOT,NTP) -> partial[ks]
// grid (GKS, GMT), 256 threads (8 warps). CTA tile 128x96; warp tile 16x96.
__global__ void __launch_bounds__(256, 1) k_gemm3() {
    extern __shared__ char dsm[];
    int tid = threadIdx.x;
    int w = tid >> 5, l = tid & 31;
    int ks = blockIdx.x, mt = blockIdx.y;
    int m0 = mt * GMTILE;
    int kbase = ks * GKPER;

    const char* gA = (const char*)(g_pool + (size_t)m0*KTOT + kbase);
    const char* gB = (const char*)(g_wp2 + kbase);

    auto load_stage = [&](int s, int it) {
        char* sa = dsm + s*STG_SZ;
        char* sb = sa + SA_SZ;
        size_t koff = (size_t)it*KC*2;
        #pragma unroll
        for (int i = 0; i < 4; i++) {          // A: 128 rows x 8 chunks of 16B
            int ch = i*256 + tid;
            int row = ch >> 3, c16 = ch & 7;
            cpa16(sa + row*ROWB + c16*16, gA + (size_t)row*(KTOT*2) + koff + c16*16);
        }
        #pragma unroll
        for (int i = 0; i < 3; i++) {          // B: 96 rows x 8 chunks of 16B
            int ch = i*256 + tid;
            int row = ch >> 3, c16 = ch & 7;
            cpa16(sb + row*ROWB + c16*16, gB + (size_t)row*(KTOT*2) + koff + c16*16);
        }
    };

    float acc[12][4];
    #pragma unroll
    for (int t = 0; t < 12; t++)
        #pragma unroll
        for (int i = 0; i < 4; i++) acc[t][i] = 0.0f;

    // prologue
    #pragma unroll
    for (int s = 0; s < NSTAGE-1; s++) { load_stage(s, s); cpa_commit(); }

    int mr = l >> 2;           // lane/4
    int kc2 = (l & 3) * 2;     // (lane%4)*2

    for (int j = 0; j < NIT; j++) {
        int ldit = j + NSTAGE - 1;
        if (ldit < NIT) load_stage(ldit & (NSTAGE-1), ldit);
        cpa_commit();
        cpa_wait<NSTAGE-1>();
        __syncthreads();

        const __half* Asm = (const __half*)(dsm + (j & (NSTAGE-1))*STG_SZ);
        const __half* Bsm = (const __half*)(dsm + (j & (NSTAGE-1))*STG_SZ + SA_SZ);
        #pragma unroll
        for (int q = 0; q < 4; q++) {
            int k0 = q*16;
            uint32_t a0 = *(const uint32_t*)&Asm[(w*16 + mr)*ROWH + k0 + kc2];
            uint32_t a1 = *(const uint32_t*)&Asm[(w*16 + mr + 8)*ROWH + k0 + kc2];
            uint32_t a2 = *(const uint32_t*)&Asm[(w*16 + mr)*ROWH + k0 + 8 + kc2];
            uint32_t a3 = *(const uint32_t*)&Asm[(w*16 + mr + 8)*ROWH + k0 + 8 + kc2];
            #pragma unroll
            for (int t = 0; t < 12; t++) {
                uint32_t b0 = *(const uint32_t*)&Bsm[(t*8 + mr)*ROWH + k0 + kc2];
                uint32_t b1 = *(const uint32_t*)&Bsm[(t*8 + mr)*ROWH + k0 + 8 + kc2];
                mma16816(acc[t], a0, a1, a2, a3, b0, b1);
            }
        }
        __syncthreads();
    }

    // epilogue: D fragment (d0,d1)=(row, c..c+1), (d2,d3)=(row+8, c..c+1)
    float* po = g_partial + (size_t)ks*NR*NTP;
    int r0 = m0 + w*16 + mr;
    #pragma unroll
    for (int t = 0; t < 12; t++) {
        int c = t*8 + kc2;
        float2 lo = make_float2(acc[t][0], acc[t][1]);
        float2 hi = make_float2(acc[t][2], acc[t][3]);
        *(float2*)&po[(size_t)r0*NTP + c] = lo;
        *(float2*)&po[(size_t)(r0 + 8)*NTP + c] = hi;
    }
}

// ---------------- Kernel 5: reduce K-splits, apply 1/196 mean + bias mean
__global__ void k_reduce(const float* __restrict__ conv_b, float* __restrict__ out) {
    int idx = blockIdx.x*256 + threadIdx.x;
    if (idx >= NR*NT) return;
    int r = idx / NT, t = idx - r*NT;
    float s = 0.0f;
    #pragma unroll
    for (int ks = 0; ks < GKS; ks++)
        s += g_partial[((size_t)ks*NR + r)*NTP + t];
    s *= (1.0f/196.0f);
    float bm = 0.0f;
    for (int b = 0; b < NBINS; b++) bm += conv_b[t*NBINS + b];
    out[idx] = s + bm*(1.0f/49.0f);
}

extern "C" void kernel_launch(void* const* d_in, const int* in_sizes, int n_in,
                              void* d_out, int out_size) {
    const float* x       = (const float*)d_in[0];   // (1024, 100, 100)
    const float* regions = (const float*)d_in[1];   // (1024, 4)
    const float* conv_w  = (const float*)d_in[2];   // (3969, 1024)
    const float* conv_b  = (const float*)d_in[3];   // (3969,)
    float* out = (float*)d_out;                     // (1024, 81)

    cudaFuncSetAttribute(k_gemm3, cudaFuncAttributeMaxDynamicSharedMemorySize, SM_TOTAL);

    k_transpose<<<dim3((FH*FW + 31)/32, NC/32), dim3(32, 8)>>>(x);
    k_wprep2<<<(NTP*NBINS*16 + 255)/256, 256>>>(conv_w);
    k_pool<<<NR, 256>>>(regions);
    k_gemm3<<<dim3(GKS, GMT), 256, SM_TOTAL>>>();
    k_reduce<<<(NR*NT + 255)/256, 256>>>(conv_b, out);
}

// round 5
// speedup vs baseline: 3.1756x; 1.0275x over previous
#include <cuda_runtime.h>
#include <cuda_fp16.h>
#include <cstdint>

// Problem constants
#define FH 100
#define FW 100
#define NC 1024
#define NK 7
#define NT 81
#define NTP 96           // padded targets (B rows, zero-padded 81..95)
#define NR 1024
#define NBINS 49
#define KTOT (NBINS*NC)  // 50176

// Fused kernel tiling: grid (NBINS, 8). CTA: 1 bin, 128 regions, K=1024 in 16 chunks of 64.
#define MTILE 128
#define NCH 16           // K chunks per bin
#define KC 64            // channels per chunk

// SMEM layout
#define ROWB 144
#define ROWH 72
#define AB_OFF   0
#define AB_SZ    (MTILE*ROWB)         // 18432
#define BB_OFF   AB_SZ
#define BB_SZ    (NTP*ROWB)           // 13824 per stage, x2
#define MP_OFF   (BB_OFF + 2*BB_SZ)   // 46080: pixel byte-offsets u32 [128][16]
#define MW_OFF   (MP_OFF + MTILE*16*4) // 54272: weights f32 [128][16]
#define SM_TOTAL (MW_OFF + MTILE*16*4) // 62464

// Scratch (device globals; no allocation)
__device__ __half g_xt[FH*FW*NC];                       // (HW, C) fp16
__device__ __half g_wp2[(size_t)NTP*KTOT];              // (Tpad, bin*C) fp16, K-major
__device__ float  g_partial[(size_t)NBINS*NR*NTP];      // 19.3 MB per-bin partials

// ---------------- helpers ----------------
__device__ __forceinline__ void cpa16(void* s, const void* g) {
    uint32_t a;
    asm("{ .reg .u64 t; cvta.to.shared.u64 t, %1; cvt.u32.u64 %0, t; }" : "=r"(a) : "l"(s));
    asm volatile("cp.async.cg.shared.global [%0], [%1], 16;" :: "r"(a), "l"(g));
}
__device__ __forceinline__ void cpa_commit() { asm volatile("cp.async.commit_group;"); }
template<int N> __device__ __forceinline__ void cpa_wait() {
    asm volatile("cp.async.wait_group %0;" :: "n"(N));
}
__device__ __forceinline__ void mma16816(float* d, uint32_t a0, uint32_t a1,
                                         uint32_t a2, uint32_t a3,
                                         uint32_t b0, uint32_t b1) {
    asm volatile(
        "mma.sync.aligned.m16n8k16.row.col.f32.f16.f16.f32 "
        "{%0,%1,%2,%3}, {%4,%5,%6,%7}, {%8,%9}, {%0,%1,%2,%3};"
        : "+f"(d[0]), "+f"(d[1]), "+f"(d[2]), "+f"(d[3])
        : "r"(a0), "r"(a1), "r"(a2), "r"(a3), "r"(b0), "r"(b1));
}
__device__ __forceinline__ float2 h2f2(unsigned v) {
    __half2 h = *reinterpret_cast<__half2*>(&v);
    return __half22float2(h);
}

// ---------------- Kernel 1: transpose + convert  x(C,HW) f32 -> xt(HW,C) f16
__global__ void k_transpose(const float* __restrict__ x) {
    __shared__ float tile[32][33];
    int p0 = blockIdx.x * 32;
    int c0 = blockIdx.y * 32;
    int tx = threadIdx.x, ty = threadIdx.y;
    #pragma unroll
    for (int j = 0; j < 4; j++) {
        int c = c0 + ty + j*8;
        int p = p0 + tx;
        float v = 0.0f;
        if (p < FH*FW) v = x[c*(FH*FW) + p];
        tile[ty + j*8][tx] = v;
    }
    __syncthreads();
    #pragma unroll
    for (int j = 0; j < 4; j++) {
        int p = p0 + ty + j*8;
        int c = c0 + tx;
        if (p < FH*FW) g_xt[(size_t)p*NC + c] = __float2half(tile[tx][ty + j*8]);
    }
}

// ---------------- Kernel 2: weight permute  conv_w(T*49, C) f32 -> Wp2(Tpad, bin*C) f16
__global__ void k_wprep2(const float* __restrict__ conv_w) {
    int idx = blockIdx.x*256 + threadIdx.x;   // over NTP * NBINS * 16 (64-ch chunks)
    if (idx >= NTP*NBINS*16) return;
    int t = idx / (NBINS*16);
    int rem = idx - t*(NBINS*16);
    int bin = rem >> 4;
    int c0 = (rem & 15) * 64;
    __half* dst = g_wp2 + (size_t)t*KTOT + bin*NC + c0;
    if (t < NT) {
        const float* src = conv_w + ((size_t)t*NBINS + bin)*NC + c0;
        #pragma unroll
        for (int j = 0; j < 64; j += 8) {
            float4 f0 = *(const float4*)(src + j);
            float4 f1 = *(const float4*)(src + j + 4);
            __half2 h0 = __floats2half2_rn(f0.x, f0.y);
            __half2 h1 = __floats2half2_rn(f0.z, f0.w);
            __half2 h2 = __floats2half2_rn(f1.x, f1.y);
            __half2 h3 = __floats2half2_rn(f1.z, f1.w);
            uint4 o;
            o.x = *reinterpret_cast<unsigned*>(&h0);
            o.y = *reinterpret_cast<unsigned*>(&h1);
            o.z = *reinterpret_cast<unsigned*>(&h2);
            o.w = *reinterpret_cast<unsigned*>(&h3);
            *reinterpret_cast<uint4*>(dst + j) = o;
        }
    } else {
        uint4 z = {0u, 0u, 0u, 0u};
        #pragma unroll
        for (int j = 0; j < 64; j += 8) *reinterpret_cast<uint4*>(dst + j) = z;
    }
}

// ---------------- Kernel 3: FUSED PSROIAlign pooling + HMMA GEMM
// grid (NBINS, 8), 256 threads. CTA: bin b, regions [mt*128, +128), all T.
// Output: g_partial[b][128 rows][96] (f32), deterministic.
__global__ void __launch_bounds__(256, 1) k_poolmma(const float* __restrict__ regions) {
    extern __shared__ char dsm[];
    char* Ab  = dsm + AB_OFF;
    char* Bb  = dsm + BB_OFF;
    uint32_t* spix = (uint32_t*)(dsm + MP_OFF);
    float*    swgt = (float*)(dsm + MW_OFF);

    int tid = threadIdx.x;
    int w = tid >> 5, l = tid & 31;
    int b = blockIdx.x, mt = blockIdx.y;
    int m0 = mt * MTILE;
    int u = b / NK, v = b - u*NK;

    // ---- meta: 16 (pixel byte-offset, bilinear weight) per region ----
    if (tid < MTILE) {
        float4 reg = reinterpret_cast<const float4*>(regions)[m0 + tid];
        float top  = (reg.x - reg.z*0.5f)*(float)FH;
        float left = (reg.y - reg.w*0.5f)*(float)FW;
        float bh = reg.z*((float)FH/(float)NK);
        float bw = reg.w*((float)FW/(float)NK);
        int yi[2][2]; float wy[2][2];
        int xi[2][2]; float wx[2][2];
        #pragma unroll
        for (int s = 0; s < 2; s++) {
            float ys = top + ((float)u + (s ? 0.75f : 0.25f))*bh;
            ys = fminf(fmaxf(ys, 0.0f), 99.0f);
            float yf = floorf(ys);
            int y0 = (int)yf;
            yi[s][0] = y0; yi[s][1] = min(y0 + 1, 99);
            wy[s][1] = ys - yf; wy[s][0] = 1.0f - wy[s][1];
            float xs = left + ((float)v + (s ? 0.75f : 0.25f))*bw;
            xs = fminf(fmaxf(xs, 0.0f), 99.0f);
            float xf = floorf(xs);
            int x0 = (int)xf;
            xi[s][0] = x0; xi[s][1] = min(x0 + 1, 99);
            wx[s][1] = xs - xf; wx[s][0] = 1.0f - wx[s][1];
        }
        #pragma unroll
        for (int sy = 0; sy < 2; sy++)
        #pragma unroll
        for (int sx = 0; sx < 2; sx++)
        #pragma unroll
        for (int cy = 0; cy < 2; cy++)
        #pragma unroll
        for (int cx = 0; cx < 2; cx++) {
            int i = sy*8 + sx*4 + cy*2 + cx;
            uint32_t pix = (uint32_t)(yi[sy][cy]*FW + xi[sx][cx]);
            spix[tid*16 + i] = pix * (NC*2);          // byte offset into g_xt
            swgt[tid*16 + i] = wy[sy][cy]*wx[sx][cx];
        }
    }

    // ---- B prefetch chunk 0 ----
    const char* gB = (const char*)g_wp2 + (size_t)b*NC*2;   // + t*KTOT*2 + kc*128
    {
        #pragma unroll
        for (int i = 0; i < 3; i++) {
            int ch = i*256 + tid;
            int row = ch >> 3, c16 = ch & 7;
            cpa16(Bb + row*ROWB + c16*16, gB + (size_t)row*(KTOT*2) + c16*16);
        }
        cpa_commit();
    }
    __syncthreads();   // meta visible

    float acc[12][4];
    #pragma unroll
    for (int t = 0; t < 12; t++)
        #pragma unroll
        for (int i = 0; i < 4; i++) acc[t][i] = 0.0f;

    int r_ = tid >> 2;        // region-in-tile for gather (first task)
    int g_ = tid & 3;         // 16-ch group (32B) within chunk
    int mr = l >> 2;          // MMA fragment row
    int kc2 = (l & 3) * 2;

    const char* xbase = (const char*)g_xt + g_*32;

    for (int kc = 0; kc < NCH; kc++) {
        int s = kc & 1;
        uint32_t kb = (uint32_t)kc * 128;

        // ---- gather both tasks into registers ----
        float f0[16], f1[16];
        #pragma unroll
        for (int j = 0; j < 16; j++) { f0[j] = 0.0f; f1[j] = 0.0f; }
        #pragma unroll
        for (int i = 0; i < 16; i++) {
            uint32_t off0 = spix[r_*16 + i] + kb;
            float wv0 = swgt[r_*16 + i];
            const uint4* p0 = (const uint4*)(xbase + off0);
            uint4 d0 = p0[0], d1 = p0[1];
            float2 c;
            c = h2f2(d0.x); f0[0]  += wv0*c.x; f0[1]  += wv0*c.y;
            c = h2f2(d0.y); f0[2]  += wv0*c.x; f0[3]  += wv0*c.y;
            c = h2f2(d0.z); f0[4]  += wv0*c.x; f0[5]  += wv0*c.y;
            c = h2f2(d0.w); f0[6]  += wv0*c.x; f0[7]  += wv0*c.y;
            c = h2f2(d1.x); f0[8]  += wv0*c.x; f0[9]  += wv0*c.y;
            c = h2f2(d1.y); f0[10] += wv0*c.x; f0[11] += wv0*c.y;
            c = h2f2(d1.z); f0[12] += wv0*c.x; f0[13] += wv0*c.y;
            c = h2f2(d1.w); f0[14] += wv0*c.x; f0[15] += wv0*c.y;
        }
        #pragma unroll
        for (int i = 0; i < 16; i++) {
            uint32_t off1 = spix[(r_+64)*16 + i] + kb;
            float wv1 = swgt[(r_+64)*16 + i];
            const uint4* p1 = (const uint4*)(xbase + off1);
            uint4 d0 = p1[0], d1 = p1[1];
            float2 c;
            c = h2f2(d0.x); f1[0]  += wv1*c.x; f1[1]  += wv1*c.y;
            c = h2f2(d0.y); f1[2]  += wv1*c.x; f1[3]  += wv1*c.y;
            c = h2f2(d0.z); f1[4]  += wv1*c.x; f1[5]  += wv1*c.y;
            c = h2f2(d0.w); f1[6]  += wv1*c.x; f1[7]  += wv1*c.y;
            c = h2f2(d1.x); f1[8]  += wv1*c.x; f1[9]  += wv1*c.y;
            c = h2f2(d1.y); f1[10] += wv1*c.x; f1[11] += wv1*c.y;
            c = h2f2(d1.z); f1[12] += wv1*c.x; f1[13] += wv1*c.y;
            c = h2f2(d1.w); f1[14] += wv1*c.x; f1[15] += wv1*c.y;
        }

        cpa_wait<0>();       // B[kc] in SMEM
        __syncthreads();     // all warps done with previous MMA reads

        // ---- store A tile ----
        {
            uint4 o0, o1;
            __half2 h;
            h = __floats2half2_rn(f0[0],  f0[1]);  o0.x = *(unsigned*)&h;
            h = __floats2half2_rn(f0[2],  f0[3]);  o0.y = *(unsigned*)&h;
            h = __floats2half2_rn(f0[4],  f0[5]);  o0.z = *(unsigned*)&h;
            h = __floats2half2_rn(f0[6],  f0[7]);  o0.w = *(unsigned*)&h;
            h = __floats2half2_rn(f0[8],  f0[9]);  o1.x = *(unsigned*)&h;
            h = __floats2half2_rn(f0[10], f0[11]); o1.y = *(unsigned*)&h;
            h = __floats2half2_rn(f0[12], f0[13]); o1.z = *(unsigned*)&h;
            h = __floats2half2_rn(f0[14], f0[15]); o1.w = *(unsigned*)&h;
            *(uint4*)(Ab + r_*ROWB + g_*32) = o0;
            *(uint4*)(Ab + r_*ROWB + g_*32 + 16) = o1;
            h = __floats2half2_rn(f1[0],  f1[1]);  o0.x = *(unsigned*)&h;
            h = __floats2half2_rn(f1[2],  f1[3]);  o0.y = *(unsigned*)&h;
            h = __floats2half2_rn(f1[4],  f1[5]);  o0.z = *(unsigned*)&h;
            h = __floats2half2_rn(f1[6],  f1[7]);  o0.w = *(unsigned*)&h;
            h = __floats2half2_rn(f1[8],  f1[9]);  o1.x = *(unsigned*)&h;
            h = __floats2half2_rn(f1[10], f1[11]); o1.y = *(unsigned*)&h;
            h = __floats2half2_rn(f1[12], f1[13]); o1.z = *(unsigned*)&h;
            h = __floats2half2_rn(f1[14], f1[15]); o1.w = *(unsigned*)&h;
            *(uint4*)(Ab + (r_+64)*ROWB + g_*32) = o0;
            *(uint4*)(Ab + (r_+64)*ROWB + g_*32 + 16) = o1;
        }

        // ---- prefetch B[kc+1] into other stage ----
        if (kc < NCH-1) {
            #pragma unroll
            for (int i = 0; i < 3; i++) {
                int ch = i*256 + tid;
                int row = ch >> 3, c16 = ch & 7;
                cpa16(Bb + (s^1)*BB_SZ + row*ROWB + c16*16,
                      gB + (size_t)row*(KTOT*2) + (kc+1)*128 + c16*16);
            }
            cpa_commit();
        }
        __syncthreads();     // A visible

        // ---- MMA over this 64-K chunk ----
        const __half* Asm = (const __half*)Ab;
        const __half* Bsm = (const __half*)(Bb + s*BB_SZ);
        #pragma unroll
        for (int q = 0; q < 4; q++) {
            int k0 = q*16;
            uint32_t a0 = *(const uint32_t*)&Asm[(w*16 + mr)*ROWH + k0 + kc2];
            uint32_t a1 = *(const uint32_t*)&Asm[(w*16 + mr + 8)*ROWH + k0 + kc2];
            uint32_t a2 = *(const uint32_t*)&Asm[(w*16 + mr)*ROWH + k0 + 8 + kc2];
            uint32_t a3 = *(const uint32_t*)&Asm[(w*16 + mr + 8)*ROWH + k0 + 8 + kc2];
            #pragma unroll
            for (int t = 0; t < 12; t++) {
                uint32_t b0 = *(const uint32_t*)&Bsm[(t*8 + mr)*ROWH + k0 + kc2];
                uint32_t b1 = *(const uint32_t*)&Bsm[(t*8 + mr)*ROWH + k0 + 8 + kc2];
                mma16816(acc[t], a0, a1, a2, a3, b0, b1);
            }
        }
    }

    // ---- epilogue ----
    float* po = g_partial + (size_t)b*NR*NTP;
    int r0 = m0 + w*16 + mr;
    #pragma unroll
    for (int t = 0; t < 12; t++) {
        int c = t*8 + kc2;
        *(float2*)&po[(size_t)r0*NTP + c] = make_float2(acc[t][0], acc[t][1]);
        *(float2*)&po[(size_t)(r0 + 8)*NTP + c] = make_float2(acc[t][2], acc[t][3]);
    }
}

// ---------------- Kernel 4: reduce bins, apply 1/196 mean + bias mean
__global__ void k_reduce(const float* __restrict__ conv_b, float* __restrict__ out) {
    int idx = blockIdx.x*256 + threadIdx.x;
    if (idx >= NR*NT) return;
    int r = idx / NT, t = idx - r*NT;
    float s = 0.0f;
    #pragma unroll 7
    for (int b = 0; b < NBINS; b++)
        s += g_partial[((size_t)b*NR + r)*NTP + t];
    s *= (1.0f/196.0f);
    float bm = 0.0f;
    for (int b = 0; b < NBINS; b++) bm += conv_b[t*NBINS + b];
    out[idx] = s + bm*(1.0f/49.0f);
}

extern "C" void kernel_launch(void* const* d_in, const int* in_sizes, int n_in,
                              void* d_out, int out_size) {
    const float* x       = (const float*)d_in[0];   // (1024, 100, 100)
    const float* regions = (const float*)d_in[1];   // (1024, 4)
    const float* conv_w  = (const float*)d_in[2];   // (3969, 1024)
    const float* conv_b  = (const float*)d_in[3];   // (3969,)
    float* out = (float*)d_out;                     // (1024, 81)

    cudaFuncSetAttribute(k_poolmma, cudaFuncAttributeMaxDynamicSharedMemorySize, SM_TOTAL);

    k_transpose<<<dim3((FH*FW + 31)/32, NC/32), dim3(32, 8)>>>(x);
    k_wprep2<<<(NTP*NBINS*16 + 255)/256, 256>>>(conv_w);
    k_poolmma<<<dim3(NBINS, NR/MTILE), 256, SM_TOTAL>>>(regions);
    k_reduce<<<(NR*NT + 255)/256, 256>>>(conv_b, out);
}

// round 6
// speedup vs baseline: 3.4375x; 1.0825x over previous
#include <cuda_runtime.h>
#include <cuda_fp16.h>
#include <cstdint>

// Problem constants
#define FH 100
#define FW 100
#define NC 1024
#define NK 7
#define NT 81
#define NTP 88           // padded targets (11 n8-tiles; rows 81..87 zero)
#define NR 1024
#define NBINS 49
#define KTOT (NBINS*NC)  // 50176

// Fused kernel tiling: grid (NBINS, 8). CTA: 1 bin, 128 regions, 16 chunks of 64 ch.
#define MTILE 128
#define NCH 16
#define NTILES 11        // n8 tiles

// SMEM layout
#define ROWB 144
#define ROWH 72
#define AB_SZ    (MTILE*ROWB)            // 18432, x2 stages
#define BB_SZ    (NTP*ROWB)              // 12672, x4 stages
#define BB_OFF   (2*AB_SZ)               // 36864
#define MP_OFF   (BB_OFF + 4*BB_SZ)      // 87552
#define MW_OFF   (MP_OFF + MTILE*16*4)   // 95744
#define SM_TOTAL (MW_OFF + MTILE*16*4)   // 103936

// Scratch (device globals; no allocation)
__device__ __half g_xt[FH*FW*NC];                       // (HW, C) fp16
__device__ __half g_wp2[(size_t)NTP*KTOT];              // (Tpad, bin*C) fp16, K-major
__device__ float  g_partial[(size_t)NR*NBINS*NTP];      // (r, bin, t) f32

// ---------------- helpers ----------------
__device__ __forceinline__ void cpa16(void* s, const void* g) {
    uint32_t a;
    asm("{ .reg .u64 t; cvta.to.shared.u64 t, %1; cvt.u32.u64 %0, t; }" : "=r"(a) : "l"(s));
    asm volatile("cp.async.cg.shared.global [%0], [%1], 16;" :: "r"(a), "l"(g));
}
__device__ __forceinline__ void cpa_commit() { asm volatile("cp.async.commit_group;"); }
template<int N> __device__ __forceinline__ void cpa_wait() {
    asm volatile("cp.async.wait_group %0;" :: "n"(N));
}
__device__ __forceinline__ void mma16816(float* d, uint32_t a0, uint32_t a1,
                                         uint32_t a2, uint32_t a3,
                                         uint32_t b0, uint32_t b1) {
    asm volatile(
        "mma.sync.aligned.m16n8k16.row.col.f32.f16.f16.f32 "
        "{%0,%1,%2,%3}, {%4,%5,%6,%7}, {%8,%9}, {%0,%1,%2,%3};"
        : "+f"(d[0]), "+f"(d[1]), "+f"(d[2]), "+f"(d[3])
        : "r"(a0), "r"(a1), "r"(a2), "r"(a3), "r"(b0), "r"(b1));
}
__device__ __forceinline__ float2 h2f2(unsigned v) {
    __half2 h = *reinterpret_cast<__half2*>(&v);
    return __half22float2(h);
}

// ---------------- Kernel 1: transpose + convert  x(C,HW) f32 -> xt(HW,C) f16
__global__ void k_transpose(const float* __restrict__ x) {
    __shared__ float tile[32][33];
    int p0 = blockIdx.x * 32;
    int c0 = blockIdx.y * 32;
    int tx = threadIdx.x, ty = threadIdx.y;
    #pragma unroll
    for (int j = 0; j < 4; j++) {
        int c = c0 + ty + j*8;
        int p = p0 + tx;
        float v = 0.0f;
        if (p < FH*FW) v = x[c*(FH*FW) + p];
        tile[ty + j*8][tx] = v;
    }
    __syncthreads();
    #pragma unroll
    for (int j = 0; j < 4; j++) {
        int p = p0 + ty + j*8;
        int c = c0 + tx;
        if (p < FH*FW) g_xt[(size_t)p*NC + c] = __float2half(tile[tx][ty + j*8]);
    }
}

// ---------------- Kernel 2: weight permute  conv_w(T*49, C) f32 -> Wp2(Tpad, bin*C) f16
__global__ void k_wprep2(const float* __restrict__ conv_w) {
    int idx = blockIdx.x*256 + threadIdx.x;   // over NTP * NBINS * 16 (64-ch chunks)
    if (idx >= NTP*NBINS*16) return;
    int t = idx / (NBINS*16);
    int rem = idx - t*(NBINS*16);
    int bin = rem >> 4;
    int c0 = (rem & 15) * 64;
    __half* dst = g_wp2 + (size_t)t*KTOT + bin*NC + c0;
    if (t < NT) {
        const float* src = conv_w + ((size_t)t*NBINS + bin)*NC + c0;
        #pragma unroll
        for (int j = 0; j < 64; j += 8) {
            float4 f0 = *(const float4*)(src + j);
            float4 f1 = *(const float4*)(src + j + 4);
            __half2 h0 = __floats2half2_rn(f0.x, f0.y);
            __half2 h1 = __floats2half2_rn(f0.z, f0.w);
            __half2 h2 = __floats2half2_rn(f1.x, f1.y);
            __half2 h3 = __floats2half2_rn(f1.z, f1.w);
            uint4 o;
            o.x = *reinterpret_cast<unsigned*>(&h0);
            o.y = *reinterpret_cast<unsigned*>(&h1);
            o.z = *reinterpret_cast<unsigned*>(&h2);
            o.w = *reinterpret_cast<unsigned*>(&h3);
            *reinterpret_cast<uint4*>(dst + j) = o;
        }
    } else {
        uint4 z = {0u, 0u, 0u, 0u};
        #pragma unroll
        for (int j = 0; j < 64; j += 8) *reinterpret_cast<uint4*>(dst + j) = z;
    }
}

// ---------------- Kernel 3: FUSED PSROIAlign pooling + HMMA GEMM
__global__ void __launch_bounds__(256, 2) k_poolmma(const float* __restrict__ regions) {
    extern __shared__ char dsm[];
    char* Ab  = dsm;
    char* Bb  = dsm + BB_OFF;
    uint32_t* spix = (uint32_t*)(dsm + MP_OFF);
    float*    swgt = (float*)(dsm + MW_OFF);

    int tid = threadIdx.x;
    int w = tid >> 5, l = tid & 31;
    int b = blockIdx.x, mt = blockIdx.y;
    int m0 = mt * MTILE;
    int u = b / NK, v = b - u*NK;

    // ---- meta: 16 (pixel byte-offset, bilinear weight) per region ----
    if (tid < MTILE) {
        float4 reg = reinterpret_cast<const float4*>(regions)[m0 + tid];
        float top  = (reg.x - reg.z*0.5f)*(float)FH;
        float left = (reg.y - reg.w*0.5f)*(float)FW;
        float bh = reg.z*((float)FH/(float)NK);
        float bw = reg.w*((float)FW/(float)NK);
        int yi[2][2]; float wy[2][2];
        int xi[2][2]; float wx[2][2];
        #pragma unroll
        for (int s = 0; s < 2; s++) {
            float ys = top + ((float)u + (s ? 0.75f : 0.25f))*bh;
            ys = fminf(fmaxf(ys, 0.0f), 99.0f);
            float yf = floorf(ys);
            int y0 = (int)yf;
            yi[s][0] = y0; yi[s][1] = min(y0 + 1, 99);
            wy[s][1] = ys - yf; wy[s][0] = 1.0f - wy[s][1];
            float xs = left + ((float)v + (s ? 0.75f : 0.25f))*bw;
            xs = fminf(fmaxf(xs, 0.0f), 99.0f);
            float xf = floorf(xs);
            int x0 = (int)xf;
            xi[s][0] = x0; xi[s][1] = min(x0 + 1, 99);
            wx[s][1] = xs - xf; wx[s][0] = 1.0f - wx[s][1];
        }
        #pragma unroll
        for (int sy = 0; sy < 2; sy++)
        #pragma unroll
        for (int sx = 0; sx < 2; sx++)
        #pragma unroll
        for (int cy = 0; cy < 2; cy++)
        #pragma unroll
        for (int cx = 0; cx < 2; cx++) {
            int i = sy*8 + sx*4 + cy*2 + cx;
            uint32_t pix = (uint32_t)(yi[sy][cy]*FW + xi[sx][cx]);
            spix[tid*16 + i] = pix * (NC*2);          // byte offset into g_xt
            swgt[tid*16 + i] = wy[sy][cy]*wx[sx][cx];
        }
    }

    // ---- B prefetch chunks 0,1 into stages 0,1 ----
    const char* gB = (const char*)g_wp2 + (size_t)b*NC*2;
    #pragma unroll
    for (int pk = 0; pk < 2; pk++) {
        #pragma unroll
        for (int i = 0; i < 3; i++) {
            int ch = i*256 + tid;
            if (ch < NTP*8) {
                int row = ch >> 3, c16 = ch & 7;
                cpa16(Bb + pk*BB_SZ + row*ROWB + c16*16,
                      gB + (size_t)row*(KTOT*2) + pk*128 + c16*16);
            }
        }
        cpa_commit();
    }
    __syncthreads();   // meta visible

    float acc[NTILES][4];
    #pragma unroll
    for (int t = 0; t < NTILES; t++)
        #pragma unroll
        for (int i = 0; i < 4; i++) acc[t][i] = 0.0f;

    int r_ = tid >> 2;        // region-in-tile (first task), second = r_+64
    int g_ = tid & 3;         // 16-ch group (32B) within chunk
    int mr = l >> 2;
    int kc2 = (l & 3) * 2;

    const char* xbase = (const char*)g_xt + g_*32;

    for (int kc = 0; kc < NCH; kc++) {
        int sA = kc & 1;
        int sB = kc & 3;
        uint32_t kb = (uint32_t)kc * 128;

        // ---- gather: two sequential tasks (keeps regs <= 128) ----
        #pragma unroll
        for (int task = 0; task < 2; task++) {
            int rr = r_ + task*64;
            float f[16];
            #pragma unroll
            for (int j = 0; j < 16; j++) f[j] = 0.0f;
            #pragma unroll
            for (int i = 0; i < 16; i++) {
                uint32_t off = spix[rr*16 + i] + kb;
                float wv = swgt[rr*16 + i];
                const uint4* p = (const uint4*)(xbase + off);
                uint4 d0 = p[0], d1 = p[1];
                float2 c;
                c = h2f2(d0.x); f[0]  += wv*c.x; f[1]  += wv*c.y;
                c = h2f2(d0.y); f[2]  += wv*c.x; f[3]  += wv*c.y;
                c = h2f2(d0.z); f[4]  += wv*c.x; f[5]  += wv*c.y;
                c = h2f2(d0.w); f[6]  += wv*c.x; f[7]  += wv*c.y;
                c = h2f2(d1.x); f[8]  += wv*c.x; f[9]  += wv*c.y;
                c = h2f2(d1.y); f[10] += wv*c.x; f[11] += wv*c.y;
                c = h2f2(d1.z); f[12] += wv*c.x; f[13] += wv*c.y;
                c = h2f2(d1.w); f[14] += wv*c.x; f[15] += wv*c.y;
            }
            uint4 o0, o1;
            __half2 h;
            h = __floats2half2_rn(f[0],  f[1]);  o0.x = *(unsigned*)&h;
            h = __floats2half2_rn(f[2],  f[3]);  o0.y = *(unsigned*)&h;
            h = __floats2half2_rn(f[4],  f[5]);  o0.z = *(unsigned*)&h;
            h = __floats2half2_rn(f[6],  f[7]);  o0.w = *(unsigned*)&h;
            h = __floats2half2_rn(f[8],  f[9]);  o1.x = *(unsigned*)&h;
            h = __floats2half2_rn(f[10], f[11]); o1.y = *(unsigned*)&h;
            h = __floats2half2_rn(f[12], f[13]); o1.z = *(unsigned*)&h;
            h = __floats2half2_rn(f[14], f[15]); o1.w = *(unsigned*)&h;
            *(uint4*)(Ab + sA*AB_SZ + rr*ROWB + g_*32) = o0;
            *(uint4*)(Ab + sA*AB_SZ + rr*ROWB + g_*32 + 16) = o1;
        }

        // ---- prefetch B[kc+2] into stage (kc+2)%4 ----
        if (kc + 2 < NCH) {
            #pragma unroll
            for (int i = 0; i < 3; i++) {
                int ch = i*256 + tid;
                if (ch < NTP*8) {
                    int row = ch >> 3, c16 = ch & 7;
                    cpa16(Bb + ((kc+2)&3)*BB_SZ + row*ROWB + c16*16,
                          gB + (size_t)row*(KTOT*2) + (kc+2)*128 + c16*16);
                }
            }
        }
        cpa_commit();       // one group per iter (possibly empty)
        cpa_wait<2>();      // B[kc] resident
        __syncthreads();    // A[sA] stores visible; prev reads of A[sA]/B[sB] long done

        // ---- MMA over this 64-K chunk ----
        const __half* Asm = (const __half*)(Ab + sA*AB_SZ);
        const __half* Bsm = (const __half*)(Bb + sB*BB_SZ);
        #pragma unroll
        for (int q = 0; q < 4; q++) {
            int k0 = q*16;
            uint32_t a0 = *(const uint32_t*)&Asm[(w*16 + mr)*ROWH + k0 + kc2];
            uint32_t a1 = *(const uint32_t*)&Asm[(w*16 + mr + 8)*ROWH + k0 + kc2];
            uint32_t a2 = *(const uint32_t*)&Asm[(w*16 + mr)*ROWH + k0 + 8 + kc2];
            uint32_t a3 = *(const uint32_t*)&Asm[(w*16 + mr + 8)*ROWH + k0 + 8 + kc2];
            #pragma unroll
            for (int t = 0; t < NTILES; t++) {
                uint32_t b0 = *(const uint32_t*)&Bsm[(t*8 + mr)*ROWH + k0 + kc2];
                uint32_t b1 = *(const uint32_t*)&Bsm[(t*8 + mr)*ROWH + k0 + 8 + kc2];
                mma16816(acc[t], a0, a1, a2, a3, b0, b1);
            }
        }
    }

    // ---- epilogue: write (r, bin, t) layout ----
    int r0 = m0 + w*16 + mr;
    #pragma unroll
    for (int t = 0; t < NTILES; t++) {
        int c = t*8 + kc2;
        *(float2*)&g_partial[((size_t)r0*NBINS + b)*NTP + c] =
            make_float2(acc[t][0], acc[t][1]);
        *(float2*)&g_partial[((size_t)(r0+8)*NBINS + b)*NTP + c] =
            make_float2(acc[t][2], acc[t][3]);
    }
}

// ---------------- Kernel 4: reduce bins, apply 1/196 mean + bias mean
// grid 512, block (96,2): contiguous coalesced reads per region.
__global__ void k_reduce(const float* __restrict__ conv_b, float* __restrict__ out) {
    int t = threadIdx.x;                 // 0..95
    int r = blockIdx.x*2 + threadIdx.y;
    if (t >= NT) return;
    const float* po = g_partial + (size_t)r*NBINS*NTP + t;
    float s = 0.0f;
    #pragma unroll
    for (int b = 0; b < NBINS; b++) s += po[b*NTP];
    s *= (1.0f/196.0f);
    float bm = 0.0f;
    #pragma unroll 7
    for (int b = 0; b < NBINS; b++) bm += conv_b[t*NBINS + b];
    out[r*NT + t] = s + bm*(1.0f/49.0f);
}

extern "C" void kernel_launch(void* const* d_in, const int* in_sizes, int n_in,
                              void* d_out, int out_size) {
    const float* x       = (const float*)d_in[0];   // (1024, 100, 100)
    const float* regions = (const float*)d_in[1];   // (1024, 4)
    const float* conv_w  = (const float*)d_in[2];   // (3969, 1024)
    const float* conv_b  = (const float*)d_in[3];   // (3969,)
    float* out = (float*)d_out;                     // (1024, 81)

    cudaFuncSetAttribute(k_poolmma, cudaFuncAttributeMaxDynamicSharedMemorySize, SM_TOTAL);

    k_transpose<<<dim3((FH*FW + 31)/32, NC/32), dim3(32, 8)>>>(x);
    k_wprep2<<<(NTP*NBINS*16 + 255)/256, 256>>>(conv_w);
    k_poolmma<<<dim3(NBINS, NR/MTILE), 256, SM_TOTAL>>>(regions);
    k_reduce<<<512, dim3(96, 2)>>>(conv_b, out);
}